// round 9
// baseline (speedup 1.0000x reference)
#include <cuda_runtime.h>
#include <cuda_fp16.h>
#include <cstdint>

#define N_NODES 50000
#define N_EDGES 800000
#define ET (N_EDGES + N_NODES)
#define FDIM 128
#define HEADS 4
#define N_GRAPHS 64
#define OUT_CH 10
#define NEG 0.2f

#define GEMM_BLOCKS ((N_NODES + 127) / 128)        // 391
#define SCAN_BLOCKS ((N_NODES + 1023) / 1024)      // 49

#define AS_STRIDE 68
#define BS_STRIDE 136
#define AS_WORDS (128 * AS_STRIDE)
#define SMEM_WORDS (AS_WORDS + 64 * BS_STRIDE)
#define SMEM_BYTES ((SMEM_WORDS + 256) * 4)

// ---------------- scratch ----------------
__device__ __half2 g_h16[(size_t)N_NODES * FDIM / 2];   // h in fp16 (gather source)
__device__ float g_buf[(size_t)N_NODES * FDIM];
__device__ float g_asrc[N_NODES * HEADS];
__device__ float g_adst[N_NODES * HEADS];
__device__ int   g_counts[N_NODES];
__device__ int   g_off[N_NODES + 1];
__device__ int   g_cur[N_NODES];
__device__ int   g_csrc[ET];
__device__ int   g_bsum[64];
__device__ int   g_bbase[64];

__device__ __forceinline__ float lrelu(float x) { return x > 0.f ? x : NEG * x; }
__device__ __forceinline__ uint32_t f2tf32(float f) {
    uint32_t r;
    asm("cvt.rna.tf32.f32 %0, %1;" : "=r"(r) : "f"(f));
    return r;
}
__device__ __forceinline__ void mma16n8k8(float* d, const uint32_t* a, uint32_t b0, uint32_t b1) {
    asm volatile(
        "mma.sync.aligned.m16n8k8.row.col.f32.tf32.tf32.f32 "
        "{%0,%1,%2,%3}, {%4,%5,%6,%7}, {%8,%9}, {%0,%1,%2,%3};"
        : "+f"(d[0]), "+f"(d[1]), "+f"(d[2]), "+f"(d[3])
        : "r"(a[0]), "r"(a[1]), "r"(a[2]), "r"(a[3]), "r"(b0), "r"(b1));
}

// ---------------- init counts to 1 (self loops pre-counted) ----------------
__global__ void k_init_counts() {
    int i = blockIdx.x * blockDim.x + threadIdx.x;
    if (i < N_NODES) g_counts[i] = 1;
}

// ---------------- degree histogram (vectorized over dst half) ----------------
__global__ void k_hist(const int* __restrict__ ei) {
    const int4* dst4 = (const int4*)(ei + N_EDGES);
    for (int i = blockIdx.x * blockDim.x + threadIdx.x; i < N_EDGES / 4; i += gridDim.x * blockDim.x) {
        int4 d = dst4[i];
        atomicAdd(&g_counts[d.x], 1);
        atomicAdd(&g_counts[d.y], 1);
        atomicAdd(&g_counts[d.z], 1);
        atomicAdd(&g_counts[d.w], 1);
    }
}

// ---------------- parallel 3-phase scan ----------------
__global__ void __launch_bounds__(1024) k_scan1() {
    __shared__ int sh[1024];
    int tid = threadIdx.x;
    int i = blockIdx.x * 1024 + tid;
    int v = (i < N_NODES) ? g_counts[i] : 0;
    sh[tid] = v;
    __syncthreads();
#pragma unroll
    for (int off = 1; off < 1024; off <<= 1) {
        int t = (tid >= off) ? sh[tid - off] : 0;
        __syncthreads();
        sh[tid] += t;
        __syncthreads();
    }
    if (i < N_NODES) g_off[i] = sh[tid] - v;
    if (tid == 1023) g_bsum[blockIdx.x] = sh[1023];
}

__global__ void k_scan2() {
    __shared__ int sh[64];
    int tid = threadIdx.x;
    int v = (tid < SCAN_BLOCKS) ? g_bsum[tid] : 0;
    sh[tid] = v;
    __syncthreads();
#pragma unroll
    for (int off = 1; off < 64; off <<= 1) {
        int t = (tid >= off) ? sh[tid - off] : 0;
        __syncthreads();
        sh[tid] += t;
        __syncthreads();
    }
    if (tid < SCAN_BLOCKS) g_bbase[tid] = sh[tid] - v;
    if (tid == 63) g_off[N_NODES] = sh[63];
}

__global__ void k_scan3() {
    int i = blockIdx.x * blockDim.x + threadIdx.x;
    if (i < N_NODES) {
        int o = g_off[i] + g_bbase[i >> 10];
        g_off[i] = o;
        g_cur[i] = o;
    }
}

// ---------------- CSR scatter (grid-strided) ----------------
__global__ void k_scatter(const int* __restrict__ ei) {
    for (int i = blockIdx.x * blockDim.x + threadIdx.x; i < ET; i += gridDim.x * blockDim.x) {
        int s, d;
        if (i < N_EDGES) { s = ei[i]; d = ei[N_EDGES + i]; }
        else             { s = i - N_EDGES; d = s; }
        int pos = atomicAdd(&g_cur[d], 1);
        g_csrc[pos] = s;
    }
}

// ---------------- tensor-core tf32 GEMM + fused attention dots, fp16 h output ----------------
__global__ void __launch_bounds__(256) k_gemm(const float* __restrict__ Xext,
                                              const float* __restrict__ W,
                                              const float* __restrict__ att_s,
                                              const float* __restrict__ att_d) {
    extern __shared__ uint32_t sm[];
    uint32_t* As = sm;                 // [128][68]
    uint32_t* Bs = sm + AS_WORDS;      // [64][136]
    float* as_sm = (float*)(sm + SMEM_WORDS);
    float* ad_sm = as_sm + 128;
    const float* X = Xext ? Xext : (const float*)g_buf;
    const int tid = threadIdx.x;
    const int wid = tid >> 5, lane = tid & 31;
    const int g = lane >> 2, t = lane & 3;
    const int wm = wid & 3, wn = wid >> 2;
    const int row0 = blockIdx.x * 128;

    if (tid < 128)      as_sm[tid] = att_s[tid];
    else                ad_sm[tid - 128] = att_d[tid - 128];

    float d[2][8][4];
#pragma unroll
    for (int mi = 0; mi < 2; mi++)
#pragma unroll
        for (int ni = 0; ni < 8; ni++)
#pragma unroll
            for (int k = 0; k < 4; k++) d[mi][ni][k] = 0.f;

    for (int kc = 0; kc < 128; kc += 64) {
#pragma unroll
        for (int it = 0; it < 8; it++) {
            int idx = tid + it * 256;
            int r = idx >> 4, c4 = (idx & 15) * 4;
            int gr = row0 + r;
            uint32_t o0 = 0, o1 = 0, o2 = 0, o3 = 0;
            if (gr < N_NODES) {
                float4 v = *(const float4*)&X[(size_t)gr * FDIM + kc + c4];
                o0 = f2tf32(v.x); o1 = f2tf32(v.y); o2 = f2tf32(v.z); o3 = f2tf32(v.w);
            }
            uint32_t* p = &As[r * AS_STRIDE + c4];
            p[0] = o0; p[1] = o1; p[2] = o2; p[3] = o3;
        }
#pragma unroll
        for (int it = 0; it < 8; it++) {
            int idx = tid + it * 256;
            int k = idx >> 5, n4 = (idx & 31) * 4;
            float4 v = *(const float4*)&W[(size_t)(kc + k) * FDIM + n4];
            uint32_t* p = &Bs[k * BS_STRIDE + n4];
            p[0] = f2tf32(v.x); p[1] = f2tf32(v.y); p[2] = f2tf32(v.z); p[3] = f2tf32(v.w);
        }
        __syncthreads();

#pragma unroll
        for (int ks = 0; ks < 8; ks++) {
            const int k0 = ks * 8;
            uint32_t a[2][4];
#pragma unroll
            for (int mi = 0; mi < 2; mi++) {
                int rb = wm * 32 + mi * 16;
                a[mi][0] = As[(rb + g) * AS_STRIDE + k0 + t];
                a[mi][1] = As[(rb + g + 8) * AS_STRIDE + k0 + t];
                a[mi][2] = As[(rb + g) * AS_STRIDE + k0 + t + 4];
                a[mi][3] = As[(rb + g + 8) * AS_STRIDE + k0 + t + 4];
            }
#pragma unroll
            for (int ni = 0; ni < 8; ni++) {
                int nb = wn * 64 + ni * 8;
                uint32_t b0 = Bs[(k0 + t) * BS_STRIDE + nb + g];
                uint32_t b1 = Bs[(k0 + t + 4) * BS_STRIDE + nb + g];
                mma16n8k8(d[0][ni], a[0], b0, b1);
                mma16n8k8(d[1][ni], a[1], b0, b1);
            }
        }
        __syncthreads();
    }

    // epilogue: fp16 h store + fused per-head attention dots
    const int h0 = 2 * wn;
#pragma unroll
    for (int mi = 0; mi < 2; mi++) {
        int r0 = row0 + wm * 32 + mi * 16 + g;
        int r1 = r0 + 8;
        float s0a = 0.f, s0b = 0.f, d0a = 0.f, d0b = 0.f;
        float s1a = 0.f, s1b = 0.f, d1a = 0.f, d1b = 0.f;
#pragma unroll
        for (int ni = 0; ni < 8; ni++) {
            int col = wn * 64 + ni * 8 + t * 2;
            float w0s = as_sm[col], w1s = as_sm[col + 1];
            float w0d = ad_sm[col], w1d = ad_sm[col + 1];
            float v00 = d[mi][ni][0], v01 = d[mi][ni][1];
            float v10 = d[mi][ni][2], v11 = d[mi][ni][3];
            if (r0 < N_NODES) g_h16[((size_t)r0 * FDIM + col) >> 1] = __floats2half2_rn(v00, v01);
            if (r1 < N_NODES) g_h16[((size_t)r1 * FDIM + col) >> 1] = __floats2half2_rn(v10, v11);
            if (ni < 4) {
                s0a = fmaf(v00, w0s, fmaf(v01, w1s, s0a));
                d0a = fmaf(v00, w0d, fmaf(v01, w1d, d0a));
                s1a = fmaf(v10, w0s, fmaf(v11, w1s, s1a));
                d1a = fmaf(v10, w0d, fmaf(v11, w1d, d1a));
            } else {
                s0b = fmaf(v00, w0s, fmaf(v01, w1s, s0b));
                d0b = fmaf(v00, w0d, fmaf(v01, w1d, d0b));
                s1b = fmaf(v10, w0s, fmaf(v11, w1s, s1b));
                d1b = fmaf(v10, w0d, fmaf(v11, w1d, d1b));
            }
        }
#pragma unroll
        for (int o = 1; o <= 2; o <<= 1) {
            s0a += __shfl_down_sync(0xffffffffu, s0a, o);
            s0b += __shfl_down_sync(0xffffffffu, s0b, o);
            d0a += __shfl_down_sync(0xffffffffu, d0a, o);
            d0b += __shfl_down_sync(0xffffffffu, d0b, o);
            s1a += __shfl_down_sync(0xffffffffu, s1a, o);
            s1b += __shfl_down_sync(0xffffffffu, s1b, o);
            d1a += __shfl_down_sync(0xffffffffu, d1a, o);
            d1b += __shfl_down_sync(0xffffffffu, d1b, o);
        }
        if (t == 0) {
            if (r0 < N_NODES) {
                g_asrc[r0 * HEADS + h0] = s0a; g_asrc[r0 * HEADS + h0 + 1] = s0b;
                g_adst[r0 * HEADS + h0] = d0a; g_adst[r0 * HEADS + h0 + 1] = d0b;
            }
            if (r1 < N_NODES) {
                g_asrc[r1 * HEADS + h0] = s1a; g_asrc[r1 * HEADS + h0 + 1] = s1b;
                g_adst[r1 * HEADS + h0] = d1a; g_adst[r1 * HEADS + h0 + 1] = d1b;
            }
        }
    }
}

// ---------------- segment softmax + weighted aggregation (warp per dst node) ----------------
__global__ void __launch_bounds__(256) k_aggregate(const float* __restrict__ bias) {
    int d = (blockIdx.x * 256 + threadIdx.x) >> 5;
    int lane = threadIdx.x & 31;
    if (d >= N_NODES) return;
    const int beg = g_off[d], end = g_off[d + 1];

    float4 adv = *(const float4*)&g_adst[d * HEADS];
    const float ad0 = adv.x, ad1 = adv.y, ad2 = adv.z, ad3 = adv.w;

    float ea0, ea1, ea2, ea3, eb0, eb1, eb2, eb3;
    float m0 = -1e30f, m1 = -1e30f, m2 = -1e30f, m3 = -1e30f;
    int B = 0;
    for (int j = beg + lane; j < end; j += 32) {
        int s = g_csrc[j];
        float4 as = *(const float4*)&g_asrc[s * HEADS];
        float v0 = lrelu(as.x + ad0), v1 = lrelu(as.y + ad1);
        float v2 = lrelu(as.z + ad2), v3 = lrelu(as.w + ad3);
        if (B == 0)      { ea0 = v0; ea1 = v1; ea2 = v2; ea3 = v3; }
        else if (B == 1) { eb0 = v0; eb1 = v1; eb2 = v2; eb3 = v3; }
        m0 = fmaxf(m0, v0); m1 = fmaxf(m1, v1);
        m2 = fmaxf(m2, v2); m3 = fmaxf(m3, v3);
        B++;
    }
#pragma unroll
    for (int o = 16; o; o >>= 1) {
        m0 = fmaxf(m0, __shfl_xor_sync(0xffffffffu, m0, o));
        m1 = fmaxf(m1, __shfl_xor_sync(0xffffffffu, m1, o));
        m2 = fmaxf(m2, __shfl_xor_sync(0xffffffffu, m2, o));
        m3 = fmaxf(m3, __shfl_xor_sync(0xffffffffu, m3, o));
    }
    float s0 = 0.f, s1 = 0.f, s2 = 0.f, s3 = 0.f;
    if (B >= 1) {
        s0 += __expf(ea0 - m0); s1 += __expf(ea1 - m1);
        s2 += __expf(ea2 - m2); s3 += __expf(ea3 - m3);
    }
    if (B >= 2) {
        s0 += __expf(eb0 - m0); s1 += __expf(eb1 - m1);
        s2 += __expf(eb2 - m2); s3 += __expf(eb3 - m3);
    }
    for (int j = beg + lane + 64; j < end; j += 32) {
        int s = g_csrc[j];
        float4 as = *(const float4*)&g_asrc[s * HEADS];
        s0 += __expf(lrelu(as.x + ad0) - m0);
        s1 += __expf(lrelu(as.y + ad1) - m1);
        s2 += __expf(lrelu(as.z + ad2) - m2);
        s3 += __expf(lrelu(as.w + ad3) - m3);
    }
#pragma unroll
    for (int o = 16; o; o >>= 1) {
        s0 += __shfl_xor_sync(0xffffffffu, s0, o);
        s1 += __shfl_xor_sync(0xffffffffu, s1, o);
        s2 += __shfl_xor_sync(0xffffffffu, s2, o);
        s3 += __shfl_xor_sync(0xffffffffu, s3, o);
    }

    const int myh = lane >> 3;
    const float mh  = (myh == 0) ? m0 : (myh == 1) ? m1 : (myh == 2) ? m2 : m3;
    const float sh  = (myh == 0) ? s0 : (myh == 1) ? s1 : (myh == 2) ? s2 : s3;
    const float adm = (myh == 0) ? ad0 : (myh == 1) ? ad1 : (myh == 2) ? ad2 : ad3;
    const float inv = 1.f / sh;
    const float* __restrict__ asr = (const float*)g_asrc;
    const int ch = lane * 4;

    float4 acc0 = make_float4(0.f, 0.f, 0.f, 0.f);
    float4 acc1 = make_float4(0.f, 0.f, 0.f, 0.f);
    int j = beg;
    for (; j + 8 <= end; j += 8) {
        int sI[8];
#pragma unroll
        for (int u = 0; u < 8; u++) sI[u] = g_csrc[j + u];
        float aI[8];
#pragma unroll
        for (int u = 0; u < 8; u++) aI[u] = asr[sI[u] * HEADS + myh];
        uint2 hr[8];
#pragma unroll
        for (int u = 0; u < 8; u++)
            hr[u] = *(const uint2*)&g_h16[((size_t)sI[u] * FDIM + ch) >> 1];
        float al[8];
#pragma unroll
        for (int u = 0; u < 8; u++) al[u] = __expf(lrelu(aI[u] + adm) - mh) * inv;
#pragma unroll
        for (int u = 0; u < 8; u += 2) {
            float2 p0 = __half22float2(*(__half2*)&hr[u].x);
            float2 p1 = __half22float2(*(__half2*)&hr[u].y);
            float2 q0 = __half22float2(*(__half2*)&hr[u + 1].x);
            float2 q1 = __half22float2(*(__half2*)&hr[u + 1].y);
            acc0.x = fmaf(al[u], p0.x, acc0.x);     acc0.y = fmaf(al[u], p0.y, acc0.y);
            acc0.z = fmaf(al[u], p1.x, acc0.z);     acc0.w = fmaf(al[u], p1.y, acc0.w);
            acc1.x = fmaf(al[u + 1], q0.x, acc1.x); acc1.y = fmaf(al[u + 1], q0.y, acc1.y);
            acc1.z = fmaf(al[u + 1], q1.x, acc1.z); acc1.w = fmaf(al[u + 1], q1.y, acc1.w);
        }
    }
    for (; j < end; j++) {
        int s = g_csrc[j];
        float a = asr[s * HEADS + myh];
        uint2 hraw = *(const uint2*)&g_h16[((size_t)s * FDIM + ch) >> 1];
        float2 p0 = __half22float2(*(__half2*)&hraw.x);
        float2 p1 = __half22float2(*(__half2*)&hraw.y);
        float al = __expf(lrelu(a + adm) - mh) * inv;
        acc0.x = fmaf(al, p0.x, acc0.x); acc0.y = fmaf(al, p0.y, acc0.y);
        acc0.z = fmaf(al, p1.x, acc0.z); acc0.w = fmaf(al, p1.y, acc0.w);
    }
    float4 b = *(const float4*)&bias[ch];
    float4 r;
    r.x = fmaxf(acc0.x + acc1.x + b.x, 0.f);
    r.y = fmaxf(acc0.y + acc1.y + b.y, 0.f);
    r.z = fmaxf(acc0.z + acc1.z + b.z, 0.f);
    r.w = fmaxf(acc0.w + acc1.w + b.w, 0.f);
    *(float4*)&g_buf[(size_t)d * FDIM + ch] = r;
}

// ---------------- global mean pool + linear head ----------------
__global__ void k_pool(const int* __restrict__ batch,
                       const float* __restrict__ w_lin,
                       const float* __restrict__ b_lin,
                       float* __restrict__ out) {
    int g = blockIdx.x;
    __shared__ int s_lo, s_hi;
    __shared__ float pooled[FDIM];
    if (threadIdx.x == 0) {
        int lo = 0, hi = N_NODES;
        while (lo < hi) { int mid = (lo + hi) >> 1; if (batch[mid] < g) lo = mid + 1; else hi = mid; }
        s_lo = lo;
        hi = N_NODES;
        while (lo < hi) { int mid = (lo + hi) >> 1; if (batch[mid] < g + 1) lo = mid + 1; else hi = mid; }
        s_hi = lo;
    }
    __syncthreads();
    int lo = s_lo, hi = s_hi;
    float a0 = 0.f, a1 = 0.f, a2 = 0.f, a3 = 0.f;
    int n = lo;
    for (; n + 4 <= hi; n += 4) {
        a0 += g_buf[(size_t)(n + 0) * FDIM + threadIdx.x];
        a1 += g_buf[(size_t)(n + 1) * FDIM + threadIdx.x];
        a2 += g_buf[(size_t)(n + 2) * FDIM + threadIdx.x];
        a3 += g_buf[(size_t)(n + 3) * FDIM + threadIdx.x];
    }
    for (; n < hi; n++) a0 += g_buf[(size_t)n * FDIM + threadIdx.x];
    float cnt = (float)(hi - lo);
    pooled[threadIdx.x] = (a0 + a1 + a2 + a3) / fmaxf(cnt, 1.f);
    __syncthreads();
    if (threadIdx.x < OUT_CH) {
        float acc = b_lin[threadIdx.x];
        for (int c = 0; c < FDIM; c++) acc += pooled[c] * w_lin[c * OUT_CH + threadIdx.x];
        out[g * OUT_CH + threadIdx.x] = acc;
    }
}

// ---------------- launch ----------------
extern "C" void kernel_launch(void* const* d_in, const int* in_sizes, int n_in,
                              void* d_out, int out_size) {
    const float* x      = (const float*)d_in[0];
    const int*   ei     = (const int*)d_in[1];
    const int*   batch  = (const int*)d_in[2];
    const float* W1     = (const float*)d_in[3];
    const float* att_s1 = (const float*)d_in[4];
    const float* att_d1 = (const float*)d_in[5];
    const float* b1     = (const float*)d_in[6];
    const float* W2     = (const float*)d_in[7];
    const float* att_s2 = (const float*)d_in[8];
    const float* att_d2 = (const float*)d_in[9];
    const float* b2     = (const float*)d_in[10];
    const float* w_lin  = (const float*)d_in[11];
    const float* b_lin  = (const float*)d_in[12];
    float* out = (float*)d_out;

    cudaFuncSetAttribute(k_gemm, cudaFuncAttributeMaxDynamicSharedMemorySize, SMEM_BYTES);

    const int NB = (N_NODES + 255) / 256;
    const int WB = (N_NODES * 32 + 255) / 256;

    k_init_counts<<<NB, 256>>>();
    k_hist<<<200, 256>>>(ei);
    k_scan1<<<SCAN_BLOCKS, 1024>>>();
    k_scan2<<<1, 64>>>();
    k_scan3<<<NB, 256>>>();

    // layer 1
    k_gemm<<<GEMM_BLOCKS, 256, SMEM_BYTES>>>(x, W1, att_s1, att_d1);
    k_scatter<<<888, 256>>>(ei);
    k_aggregate<<<WB, 256>>>(b1);

    // layer 2
    k_gemm<<<GEMM_BLOCKS, 256, SMEM_BYTES>>>(nullptr, W2, att_s2, att_d2);
    k_aggregate<<<WB, 256>>>(b2);

    k_pool<<<N_GRAPHS, 128>>>(batch, w_lin, b_lin, out);
}